// round 11
// baseline (speedup 1.0000x reference)
#include <cuda_runtime.h>

// RenderLoss: B=262144 batches x MAXC=13 corners.
// R9: two lanes per batch (even lane: corners/edges 0-6, odd: 7-12).
// Halves the per-thread MUFU chain and register footprint (x[7]/z[7] ~ 36
// regs natural, no launch_bounds cap -> no spills). Cross-pair values
// (corner0<->corner7, edge-0 normal) via warp shuffles. Warp-autonomous,
// per-warp 2496B smem buffer (input stage reused for output staging).
// ratio input elided: per-batch scale cancels under final normalization;
// per-corner q = cos(lat)*(-1/sin(lat)) > 0.

constexpr int BATCH = 262144;
constexpr int MAXC  = 13;
constexpr int TPB   = 256;
constexpr int BPB   = TPB / 2;              // 128 batches per block
constexpr int WPB   = TPB / 32;             // 8 warps
constexpr int BPW   = 16;                   // batches per warp
constexpr int WBUF  = BPW * MAXC * 3;       // 624 floats = 2496 B per warp
constexpr int IN_F4_W  = BPW * MAXC * 2 / 4;// 104 float4 per warp (input)
constexpr int OUT_F4_W = WBUF / 4;          // 156 float4 per warp (output)

__global__ __launch_bounds__(TPB) void render_loss_kernel(
    const float* __restrict__ gt,      // [B,13,2] lon,lat
    const int*   __restrict__ nums,    // [B]
    float*       __restrict__ out)     // [B,13,3]
{
    __shared__ float smf[WPB * WBUF];  // 19968 B
    const int t = threadIdx.x;
    const int w = t >> 5;
    const int l = t & 31;
    const int m = l >> 1;              // local batch (0..15)
    const int h = l & 1;               // half: 0 -> corners 0..6, 1 -> 7..12
    float* buf = smf + w * WBUF;

    const int wbase = blockIdx.x * BPB + w * BPW;  // warp's first batch
    const int num   = nums[wbase + m];             // both pair lanes same num

    // ---- Phase 1: per-warp coalesced input stage (float4) ----
    const float4* gin = reinterpret_cast<const float4*>(
        gt + (size_t)wbase * (MAXC * 2));
    float4* b4 = reinterpret_cast<float4*>(buf);
    #pragma unroll
    for (int i = 0; i < 4; i++) {
        int idx = l + i * 32;
        if (idx < IN_F4_W) b4[idx] = gin[idx];
    }
    __syncwarp();

    // ---- Phase 2a: this lane's 7 corners (global 7h .. 7h+6) ----
    // Up to the positive per-batch factor (cancelled by normalize):
    // x = sin(lon)*q, z = cos(lon)*q, q = cos(lat)*(-1/sin(lat)) > 0.
    // For h=1, j=6 is global corner 13 (doesn't exist): reads stale floats
    // inside this warp's buffer; result only feeds discarded selects.
    const float2* cp2 = reinterpret_cast<const float2*>(buf);
    float x[7], z[7];
    #pragma unroll
    for (int j = 0; j < 7; j++) {
        float2 ll = cp2[m * MAXC + 7 * h + j];   // max idx 208 < 312 (in buffer)
        float sl, cl, so, co;
        __sincosf(ll.y, &sl, &cl);   // lat in [-1.4,-0.2] -> |sin| >= 0.199
        __sincosf(ll.x, &so, &co);   // lon
        float q = cl * (-__frcp_rn(sl));
        x[j] = so * q;
        z[j] = co * q;
    }
    __syncwarp();   // input region about to be reused for output staging

    // Edge-0 normal (meaningful on even lanes; num>=4 so edge 0 = c0->c1).
    // Odd lanes compute garbage, then overwrite via shuffle from even lane.
    float n0x, n0z;
    {
        float vx = x[1] - x[0], vz = z[1] - z[0];
        float rn = rsqrtf(vx * vx + vz * vz);
        n0x = -vz * rn;
        n0z =  vx * rn;
    }
    n0x = __shfl_sync(0xffffffffu, n0x, l & ~1);
    n0z = __shfl_sync(0xffffffffu, n0z, l & ~1);

    // Cross corner: even gets partner's corner 7, odd gets partner's corner 0.
    const float crx = __shfl_sync(0xffffffffu, x[0], l ^ 1);
    const float crz = __shfl_sync(0xffffffffu, z[0], l ^ 1);
    const float c0x = h ? crx : x[0];   // global corner 0 for wrap targets
    const float c0z = h ? crz : z[0];

    // ---- Phase 2b: 7 edges, staged straight into smem (no o[] arrays) ----
    float* ob = buf + m * (MAXC * 3);
    #pragma unroll
    for (int jl = 0; jl < 7; jl++) {
        const int jj = 7 * h + jl;               // global row/edge index

        float nx_ = (jl == 6) ? crx : x[jl + 1]; // natural next corner
        float nz_ = (jl == 6) ? crz : z[jl + 1];

        const bool wrap  = (jj + 1 == num);      // edge wraps to corner 0
        const bool valid = (jj < num);

        float tx = wrap ? c0x : nx_;
        float tz = wrap ? c0z : nz_;

        float vx = valid ? (tx - x[jl]) : 1.0f;  // invalid -> vec=(1,0,0)
        float vz = valid ? (tz - z[jl]) : 0.0f;

        float rn = rsqrtf(vx * vx + vz * vz);
        float nx = -vz * rn;
        float nz =  vx * rn;

        float px = valid ? nx : ((jj == num) ? n0x : 0.0f);
        float pz = valid ? nz : ((jj == num) ? n0z : 0.0f);

        if (jj < MAXC) {                         // odd lane's jl=6 is dummy
            ob[3 * jj + 0] = px;
            ob[3 * jj + 1] = 0.0f;
            ob[3 * jj + 2] = pz;
        }
    }
    __syncwarp();

    // ---- Phase 3: single coalesced float4 store of the warp's 16 batches ----
    const float4* s4 = reinterpret_cast<const float4*>(buf);
    float4* gout = reinterpret_cast<float4*>(
        out + (size_t)wbase * (MAXC * 3));
    #pragma unroll
    for (int i = 0; i < 5; i++) {
        int idx = l + i * 32;
        if (idx < OUT_F4_W) gout[idx] = s4[idx];
    }
}

extern "C" void kernel_launch(void* const* d_in, const int* in_sizes, int n_in,
                              void* d_out, int out_size)
{
    const float* gt    = (const float*)d_in[0];  // GT_up [B,13,2] f32
    const int*   nums  = (const int*)  d_in[1];  // corner_nums [B] i32
    // d_in[2] (up_down_ratio) cancels under normalization -> unused.
    float*       outp  = (float*)d_out;          // [B,13,3] f32

    render_loss_kernel<<<BATCH / BPB, TPB>>>(gt, nums, outp);
}

// round 12
// speedup vs baseline: 1.1544x; 1.1544x over previous
#include <cuda_runtime.h>
#include <cstdint>

// RenderLoss: B=262144 batches x MAXC=13 corners.
// R10 = R4 skeleton (1 thread/batch, warp-autonomous, 32 batches/warp) with
// pipe-rebalancing:
//  - lat sin/cos via Taylor polys on the FMA pipe (lat in [-1.4,-0.2], no
//    range reduction; err ~1e-6). MUFU keeps only lon sincos + rsqrt.
//  - division-free edges: direction invariant under positive scale
//    sl_j*sl_t (>0 since both sins negative) -> vx = a_j*s_t - a_t*s_j,
//    a = sin(lon)cos(lat), b = cos(lon)cos(lat), s = sin(lat).
//    (ratio input also cancels under the final normalize -> unused.)
//  - output staged per-edge into smem (no ox/oz register arrays), then one
//    cp.async.bulk (smem->global, 4992B) per warp replaces LDS.128+STG.128.

constexpr int BATCH = 262144;
constexpr int MAXC  = 13;
constexpr int TPB   = 256;
constexpr int WPB   = TPB / 32;             // 8 warps
constexpr int WBUF  = 32 * MAXC * 3;        // 1248 floats = 4992 B per warp
constexpr int IN_F4_W = 32 * MAXC * 2 / 4;  // 208 float4 per warp (input)

__device__ __forceinline__ uint32_t smem_u32(const void* p) {
    uint32_t a;
    asm("{ .reg .u64 t; cvta.to.shared.u64 t, %1; cvt.u32.u64 %0, t; }"
        : "=r"(a) : "l"(p));
    return a;
}

__global__ __launch_bounds__(TPB) void render_loss_kernel(
    const float* __restrict__ gt,      // [B,13,2] lon,lat
    const int*   __restrict__ nums,    // [B]
    float*       __restrict__ out)     // [B,13,3]
{
    __shared__ __align__(16) float smf[WPB * WBUF];  // 39936 B
    const int t = threadIdx.x;
    const int w = t >> 5;
    const int l = t & 31;
    float* buf = smf + w * WBUF;

    const int wbase = blockIdx.x * TPB + w * 32;   // first batch of this warp
    const int num   = nums[wbase + l];

    // ---- Phase 1: per-warp coalesced input stage (float4) ----
    const float4* gin = reinterpret_cast<const float4*>(
        gt + (size_t)wbase * (MAXC * 2));
    float4* b4 = reinterpret_cast<float4*>(buf);
    #pragma unroll
    for (int i = 0; i < 7; i++) {
        int idx = l + i * 32;
        if (idx < IN_F4_W) b4[idx] = gin[idx];
    }
    __syncwarp();

    // Lane's 13 (lon,lat) pairs -> registers.
    float2 c[MAXC];
    const float2* cp = reinterpret_cast<const float2*>(buf + l * (MAXC * 2));
    #pragma unroll
    for (int j = 0; j < MAXC; j++) c[j] = cp[j];
    __syncwarp();   // input region about to be reused for output staging

    // Corner -> (a, b, s): a = sin(lon)cos(lat), b = cos(lon)cos(lat),
    // s = sin(lat). lat polys on FMA pipe; lon on MUFU.
    auto corner = [&](float2 ll, float& a, float& b, float& s) {
        float so, co;
        __sincosf(ll.x, &so, &co);              // lon (MUFU)
        const float t2 = ll.y * ll.y;
        float sp = fmaf(t2, 2.7557319e-6f, -1.9841270e-4f);
        sp = fmaf(t2, sp, 8.3333333e-3f);
        sp = fmaf(t2, sp, -0.16666667f);
        s  = ll.y * fmaf(t2, sp, 1.0f);         // sin(lat), err ~1e-6
        float cq = fmaf(t2, -2.7557319e-7f, 2.4801587e-5f);
        cq = fmaf(t2, cq, -1.3888889e-3f);
        cq = fmaf(t2, cq, 4.1666667e-2f);
        const float cl = fmaf(t2, cq, -0.5f) * t2 + 1.0f;  // cos(lat)
        a = so * cl;
        b = co * cl;
    };

    // ---- Phase 2: edges, staged straight into smem ----
    float a0, b0, s0;
    corner(c[0], a0, b0, s0);
    float ca = a0, cb = b0, cs = s0;            // current corner
    float n0x = 0.f, n0z = 0.f;

    float* ob = buf + l * (MAXC * 3);           // stride 39 -> conflict-free STS

    #pragma unroll
    for (int j = 0; j < MAXC; j++) {
        float na = a0, nb = b0, ns = s0;        // safe default (used when j=12)
        if (j + 1 < MAXC) corner(c[j + 1], na, nb, ns);

        const bool wrap  = (j + 1 == num);      // edge wraps back to corner 0
        const bool valid = (j < num);

        const float ta = wrap ? a0 : na;
        const float tb = wrap ? b0 : nb;
        const float ts = wrap ? s0 : ns;

        // Edge vector scaled by positive cs*ts: direction preserved.
        float vx = valid ? fmaf(ca, ts, -ta * cs) : 1.0f;
        float vz = valid ? fmaf(cb, ts, -tb * cs) : 0.0f;

        const float rn = rsqrtf(fmaf(vx, vx, vz * vz));
        const float nx = -vz * rn;
        const float nz =  vx * rn;

        if (j == 0) { n0x = nx; n0z = nz; }     // num>=4 -> edge 0 always valid

        const float px = valid ? nx : ((j == num) ? n0x : 0.0f);
        const float pz = valid ? nz : ((j == num) ? n0z : 0.0f);

        ob[3 * j + 0] = px;
        ob[3 * j + 1] = 0.0f;
        ob[3 * j + 2] = pz;

        ca = na; cb = nb; cs = ns;
    }
    __syncwarp();   // all lanes' STS done before the bulk read

    // ---- Phase 3: one async bulk store (smem -> global) per warp ----
    if (l == 0) {
        asm volatile("fence.proxy.async.shared::cta;" ::: "memory");
        float* gdst = out + (size_t)wbase * (MAXC * 3);   // 4992B-aligned
        uint32_t sbuf = smem_u32(buf);
        asm volatile(
            "cp.async.bulk.global.shared::cta.bulk_group [%0], [%1], %2;"
            :: "l"(gdst), "r"(sbuf), "r"(WBUF * 4) : "memory");
        asm volatile("cp.async.bulk.commit_group;" ::: "memory");
        asm volatile("cp.async.bulk.wait_group 0;" ::: "memory");
    }
}

extern "C" void kernel_launch(void* const* d_in, const int* in_sizes, int n_in,
                              void* d_out, int out_size)
{
    const float* gt    = (const float*)d_in[0];  // GT_up [B,13,2] f32
    const int*   nums  = (const int*)  d_in[1];  // corner_nums [B] i32
    // d_in[2] (up_down_ratio) cancels under normalization -> unused.
    float*       outp  = (float*)d_out;          // [B,13,3] f32

    render_loss_kernel<<<BATCH / TPB, TPB>>>(gt, nums, outp);
}

// round 14
// speedup vs baseline: 1.1572x; 1.0025x over previous
#include <cuda_runtime.h>
#include <cstdint>

// RenderLoss: B=262144 batches x MAXC=13 corners.
// R11 = R10 (FMA-pipe lat polys, division-free edges, direct smem staging,
// per-warp cp.async.bulk store) with TPB 256 -> 64. The kernel is fully
// warp-autonomous, so small blocks smooth the scheduling tail: 21 blocks/SM
// (42 warps) and a 988-block remainder spread ~6.7/SM instead of a 284-block
// second wave at ~2/SM.

constexpr int BATCH = 262144;
constexpr int MAXC  = 13;
constexpr int TPB   = 64;                   // 2 warps per block
constexpr int WPB   = TPB / 32;
constexpr int WBUF  = 32 * MAXC * 3;        // 1248 floats = 4992 B per warp
constexpr int IN_F4_W = 32 * MAXC * 2 / 4;  // 208 float4 per warp (input)

__device__ __forceinline__ uint32_t smem_u32(const void* p) {
    uint32_t a;
    asm("{ .reg .u64 t; cvta.to.shared.u64 t, %1; cvt.u32.u64 %0, t; }"
        : "=r"(a) : "l"(p));
    return a;
}

__global__ __launch_bounds__(TPB) void render_loss_kernel(
    const float* __restrict__ gt,      // [B,13,2] lon,lat
    const int*   __restrict__ nums,    // [B]
    float*       __restrict__ out)     // [B,13,3]
{
    __shared__ __align__(16) float smf[WPB * WBUF];  // 9984 B
    const int t = threadIdx.x;
    const int w = t >> 5;
    const int l = t & 31;
    float* buf = smf + w * WBUF;

    const int wbase = blockIdx.x * TPB + w * 32;   // first batch of this warp
    const int num   = nums[wbase + l];

    // ---- Phase 1: per-warp coalesced input stage (float4) ----
    const float4* gin = reinterpret_cast<const float4*>(
        gt + (size_t)wbase * (MAXC * 2));
    float4* b4 = reinterpret_cast<float4*>(buf);
    #pragma unroll
    for (int i = 0; i < 7; i++) {
        int idx = l + i * 32;
        if (idx < IN_F4_W) b4[idx] = gin[idx];
    }
    __syncwarp();

    // Lane's 13 (lon,lat) pairs -> registers.
    float2 c[MAXC];
    const float2* cp = reinterpret_cast<const float2*>(buf + l * (MAXC * 2));
    #pragma unroll
    for (int j = 0; j < MAXC; j++) c[j] = cp[j];
    __syncwarp();   // input region about to be reused for output staging

    // Corner -> (a, b, s): a = sin(lon)cos(lat), b = cos(lon)cos(lat),
    // s = sin(lat). lat polys on the FMA pipe; lon sincos on MUFU.
    auto corner = [&](float2 ll, float& a, float& b, float& s) {
        float so, co;
        __sincosf(ll.x, &so, &co);              // lon (MUFU)
        const float t2 = ll.y * ll.y;
        float sp = fmaf(t2, 2.7557319e-6f, -1.9841270e-4f);
        sp = fmaf(t2, sp, 8.3333333e-3f);
        sp = fmaf(t2, sp, -0.16666667f);
        s  = ll.y * fmaf(t2, sp, 1.0f);         // sin(lat), err ~1e-6
        float cq = fmaf(t2, -2.7557319e-7f, 2.4801587e-5f);
        cq = fmaf(t2, cq, -1.3888889e-3f);
        cq = fmaf(t2, cq, 4.1666667e-2f);
        const float cl = fmaf(t2, cq, -0.5f) * t2 + 1.0f;  // cos(lat)
        a = so * cl;
        b = co * cl;
    };

    // ---- Phase 2: edges, staged straight into smem ----
    float a0, b0, s0;
    corner(c[0], a0, b0, s0);
    float ca = a0, cb = b0, cs = s0;            // current corner
    float n0x = 0.f, n0z = 0.f;

    float* ob = buf + l * (MAXC * 3);           // stride 39 -> conflict-free STS

    #pragma unroll
    for (int j = 0; j < MAXC; j++) {
        float na = a0, nb = b0, ns = s0;        // safe default (used when j=12)
        if (j + 1 < MAXC) corner(c[j + 1], na, nb, ns);

        const bool wrap  = (j + 1 == num);      // edge wraps back to corner 0
        const bool valid = (j < num);

        const float ta = wrap ? a0 : na;
        const float tb = wrap ? b0 : nb;
        const float ts = wrap ? s0 : ns;

        // Edge vector scaled by positive cs*ts: direction preserved.
        float vx = valid ? fmaf(ca, ts, -ta * cs) : 1.0f;
        float vz = valid ? fmaf(cb, ts, -tb * cs) : 0.0f;

        const float rn = rsqrtf(fmaf(vx, vx, vz * vz));
        const float nx = -vz * rn;
        const float nz =  vx * rn;

        if (j == 0) { n0x = nx; n0z = nz; }     // num>=4 -> edge 0 always valid

        const float px = valid ? nx : ((j == num) ? n0x : 0.0f);
        const float pz = valid ? nz : ((j == num) ? n0z : 0.0f);

        ob[3 * j + 0] = px;
        ob[3 * j + 1] = 0.0f;
        ob[3 * j + 2] = pz;

        ca = na; cb = nb; cs = ns;
    }
    __syncwarp();   // all lanes' STS done before the bulk read

    // ---- Phase 3: one async bulk store (smem -> global) per warp ----
    if (l == 0) {
        asm volatile("fence.proxy.async.shared::cta;" ::: "memory");
        float* gdst = out + (size_t)wbase * (MAXC * 3);   // 4992B-aligned
        uint32_t sbuf = smem_u32(buf);
        asm volatile(
            "cp.async.bulk.global.shared::cta.bulk_group [%0], [%1], %2;"
            :: "l"(gdst), "r"(sbuf), "r"(WBUF * 4) : "memory");
        asm volatile("cp.async.bulk.commit_group;" ::: "memory");
        asm volatile("cp.async.bulk.wait_group 0;" ::: "memory");
    }
}

extern "C" void kernel_launch(void* const* d_in, const int* in_sizes, int n_in,
                              void* d_out, int out_size)
{
    const float* gt    = (const float*)d_in[0];  // GT_up [B,13,2] f32
    const int*   nums  = (const int*)  d_in[1];  // corner_nums [B] i32
    // d_in[2] (up_down_ratio) cancels under normalization -> unused.
    float*       outp  = (float*)d_out;          // [B,13,3] f32

    render_loss_kernel<<<BATCH / TPB, TPB>>>(gt, nums, outp);
}

// round 15
// speedup vs baseline: 1.1775x; 1.0175x over previous
#include <cuda_runtime.h>
#include <cstdint>

// RenderLoss: B=262144 batches x MAXC=13 corners.
// R12 = R11 (TPB=64, FMA-pipe lat polys, division-free edges, direct smem
// staging, per-warp cp.async.bulk store) + f32x2 packed math:
//  - sin(lat)/cos(lat) polys evaluated as one packed Horner chain
//    (both are 1 + t2*P(t2); sin additionally * y) -> 5 fma.rn.f32x2 + 1 mul
//  - (a,b) = (sin lon, cos lon) * cos(lat) kept packed in one b64
//  - edge vector v = cab*ts - tab*cs: one mul.f32x2 + one fma.f32x2
// ~22% fewer issue slots per warp-tile; math identical.

constexpr int BATCH = 262144;
constexpr int MAXC  = 13;
constexpr int TPB   = 64;                   // 2 warps per block
constexpr int WPB   = TPB / 32;
constexpr int WBUF  = 32 * MAXC * 3;        // 1248 floats = 4992 B per warp
constexpr int IN_F4_W = 32 * MAXC * 2 / 4;  // 208 float4 per warp (input)

__device__ __forceinline__ uint32_t smem_u32(const void* p) {
    uint32_t a;
    asm("{ .reg .u64 t; cvta.to.shared.u64 t, %1; cvt.u32.u64 %0, t; }"
        : "=r"(a) : "l"(p));
    return a;
}

using ull = unsigned long long;
__device__ __forceinline__ ull pk2(float lo, float hi) {
    ull r; asm("mov.b64 %0, {%1, %2};" : "=l"(r) : "f"(lo), "f"(hi)); return r;
}
__device__ __forceinline__ void upk2(ull v, float& lo, float& hi) {
    asm("mov.b64 {%0, %1}, %2;" : "=f"(lo), "=f"(hi) : "l"(v));
}
__device__ __forceinline__ ull fma2(ull a, ull b, ull c) {
    ull d; asm("fma.rn.f32x2 %0, %1, %2, %3;" : "=l"(d) : "l"(a), "l"(b), "l"(c));
    return d;
}
__device__ __forceinline__ ull mul2(ull a, ull b) {
    ull d; asm("mul.rn.f32x2 %0, %1, %2;" : "=l"(d) : "l"(a), "l"(b));
    return d;
}

__global__ __launch_bounds__(TPB) void render_loss_kernel(
    const float* __restrict__ gt,      // [B,13,2] lon,lat
    const int*   __restrict__ nums,    // [B]
    float*       __restrict__ out)     // [B,13,3]
{
    __shared__ __align__(16) float smf[WPB * WBUF];  // 9984 B
    const int t = threadIdx.x;
    const int w = t >> 5;
    const int l = t & 31;
    float* buf = smf + w * WBUF;

    const int wbase = blockIdx.x * TPB + w * 32;   // first batch of this warp
    const int num   = nums[wbase + l];

    // ---- Phase 1: per-warp coalesced input stage (float4) ----
    const float4* gin = reinterpret_cast<const float4*>(
        gt + (size_t)wbase * (MAXC * 2));
    float4* b4 = reinterpret_cast<float4*>(buf);
    #pragma unroll
    for (int i = 0; i < 7; i++) {
        int idx = l + i * 32;
        if (idx < IN_F4_W) b4[idx] = gin[idx];
    }
    __syncwarp();

    // Lane's 13 (lon,lat) pairs -> registers.
    float2 c[MAXC];
    const float2* cp = reinterpret_cast<const float2*>(buf + l * (MAXC * 2));
    #pragma unroll
    for (int j = 0; j < MAXC; j++) c[j] = cp[j];
    __syncwarp();   // input region about to be reused for output staging

    // Corner -> packed ab = {sin(lon)cos(lat), cos(lon)cos(lat)}, s = sin(lat).
    // sin(y) = y*(1 + t2*Ps(t2)), cos(y) = 1 + t2*Pc(t2); both deg-4 in t2,
    // evaluated as ONE packed Horner chain ({sin-part, cos-part}).
    auto corner = [&](float2 ll, ull& ab, float& s) {
        float so, co;
        __sincosf(ll.x, &so, &co);              // lon (MUFU)
        const float t2 = ll.y * ll.y;
        const ull t22 = pk2(t2, t2);
        ull p = fma2(t22, pk2(-2.5052108e-8f, -2.7557319e-7f),   // 1/11!, 1/10!
                          pk2( 2.7557319e-6f,  2.4801587e-5f));  // 1/9!,  1/8!
        p = fma2(t22, p,  pk2(-1.9841270e-4f, -1.3888889e-3f));  // 1/7!,  1/6!
        p = fma2(t22, p,  pk2( 8.3333333e-3f,  4.1666667e-2f));  // 1/5!,  1/4!
        p = fma2(t22, p,  pk2(-0.16666667f,   -0.5f));           // 1/3!,  1/2!
        p = fma2(t22, p,  pk2(1.0f, 1.0f));    // {sin(y)/y, cos(y)}
        float sy, cl;
        upk2(p, sy, cl);
        s  = ll.y * sy;                         // sin(lat)
        ab = mul2(pk2(so, co), pk2(cl, cl));    // {a, b}
    };

    // ---- Phase 2: edges, staged straight into smem ----
    ull   ab0; float s0;
    corner(c[0], ab0, s0);
    ull   cab = ab0; float cs = s0;             // current corner
    float n0x = 0.f, n0z = 0.f;

    float* ob = buf + l * (MAXC * 3);           // stride 39 -> conflict-free STS

    #pragma unroll
    for (int j = 0; j < MAXC; j++) {
        ull nab = ab0; float ns = s0;           // safe default (used when j=12)
        if (j + 1 < MAXC) corner(c[j + 1], nab, ns);

        const bool wrap  = (j + 1 == num);      // edge wraps back to corner 0
        const bool valid = (j < num);

        const ull   tab = wrap ? ab0 : nab;
        const float ts  = wrap ? s0  : ns;

        // v = cab*ts - tab*cs (positive scale cs*ts preserves direction)
        ull v = fma2(cab, pk2(ts, ts), mul2(tab, pk2(-cs, -cs)));
        float vx, vz;
        upk2(v, vx, vz);
        vx = valid ? vx : 1.0f;                 // invalid -> vec=(1,0,0)
        vz = valid ? vz : 0.0f;

        const float rn = rsqrtf(fmaf(vx, vx, vz * vz));
        const float nx = -vz * rn;
        const float nz =  vx * rn;

        if (j == 0) { n0x = nx; n0z = nz; }     // num>=4 -> edge 0 always valid

        const float px = valid ? nx : ((j == num) ? n0x : 0.0f);
        const float pz = valid ? nz : ((j == num) ? n0z : 0.0f);

        ob[3 * j + 0] = px;
        ob[3 * j + 1] = 0.0f;
        ob[3 * j + 2] = pz;

        cab = nab; cs = ns;
    }
    __syncwarp();   // all lanes' STS done before the bulk read

    // ---- Phase 3: one async bulk store (smem -> global) per warp ----
    if (l == 0) {
        asm volatile("fence.proxy.async.shared::cta;" ::: "memory");
        float* gdst = out + (size_t)wbase * (MAXC * 3);   // 4992B-aligned
        uint32_t sbuf = smem_u32(buf);
        asm volatile(
            "cp.async.bulk.global.shared::cta.bulk_group [%0], [%1], %2;"
            :: "l"(gdst), "r"(sbuf), "r"(WBUF * 4) : "memory");
        asm volatile("cp.async.bulk.commit_group;" ::: "memory");
        asm volatile("cp.async.bulk.wait_group 0;" ::: "memory");
    }
}

extern "C" void kernel_launch(void* const* d_in, const int* in_sizes, int n_in,
                              void* d_out, int out_size)
{
    const float* gt    = (const float*)d_in[0];  // GT_up [B,13,2] f32
    const int*   nums  = (const int*)  d_in[1];  // corner_nums [B] i32
    // d_in[2] (up_down_ratio) cancels under normalization -> unused.
    float*       outp  = (float*)d_out;          // [B,13,3] f32

    render_loss_kernel<<<BATCH / TPB, TPB>>>(gt, nums, outp);
}